// round 16
// baseline (speedup 1.0000x reference)
#include <cuda_runtime.h>
#include <stdint.h>

// VTM downsampler — VERTICAL-FIRST separable form, one kernel.
// Stage A: per input column, vertical 6-tap (4 phases x 2 bands, unscaled ints)
//          -> smem v[col][12] (slots bl*4+q), conflict-free 48B stride.
// Stage B: per output col-tile, horizontal 6-tap on v via LDS.128 windows.
// Order swap is exact: all sums are integers < 2^24 (reference's inter-pass
// trunc is a no-op), and the bilinear form commutes.
// Final: coeffs pre-scaled by 2^-14 (2^-7 on the vertical-delta row, absorbing
// its 128x), bias 0.5 seeded; cvt.rzi.sat.u8 == clip(floor(.),0,255).
//
// integer = i>>2, frac = 4*(i&3) -> FILTER rows {0,4,8,12}, taps k=3..8.

#define IH 1080
#define IW 1920
#define OH 540
#define OW 960
#define NIMG 24
#define NC 243           // input cols 0..242 ever needed
#define VS 12            // v slots per col (8 used) -> 48B stride, 16B aligned

#define S14 6.103515625e-5f   // 2^-14
#define S7  7.8125e-3f        // 2^-7 (vertical-delta row: 128x folded in)

// 6-tap chains, coeffs scaled by S, bias 0.5 seeded (phases 1,2,3)
#define Q1(S,a0,a1,a2,a3,a4,a5) fmaf(5.f*(S),(a0), fmaf(-18.f*(S),(a1), fmaf(114.f*(S),(a2), \
                                 fmaf(36.f*(S),(a3), fmaf(-10.f*(S),(a4), fmaf((S),(a5),0.5f))))))
#define Q2(S,a0,a1,a2,a3,a4,a5) fmaf(4.f*(S),((a0)+(a5)), fmaf(-19.f*(S),((a1)+(a4)), \
                                 fmaf(79.f*(S),((a2)+(a3)),0.5f)))
#define Q3(S,a0,a1,a2,a3,a4,a5) fmaf(5.f*(S),(a5), fmaf(-18.f*(S),(a4), fmaf(114.f*(S),(a3), \
                                 fmaf(36.f*(S),(a2), fmaf(-10.f*(S),(a1), fmaf((S),(a0),0.5f))))))
// unscaled integer chains (vertical, stage A)
#define U1(a0,a1,a2,a3,a4,a5) fmaf(5.f,(a0), fmaf(-18.f,(a1), fmaf(114.f,(a2), \
                              fmaf(36.f,(a3), fmaf(-10.f,(a4),(a5))))))
#define U2(a0,a1,a2,a3,a4,a5) fmaf(4.f,((a0)+(a5)), fmaf(-19.f,((a1)+(a4)), 79.f*((a2)+(a3))))
#define U3(a0,a1,a2,a3,a4,a5) fmaf(5.f,(a5), fmaf(-18.f,(a4), fmaf(114.f,(a3), \
                              fmaf(36.f,(a2), fmaf(-10.f,(a1),(a0))))))

// clip(floor(v),0,255) via saturating u8 truncate
__device__ __forceinline__ float fin(float v) {
    unsigned short t; asm("cvt.rzi.sat.u8.f32 %0,%1;" : "=h"(t) : "f"(v));
    float o;          asm("cvt.rn.f32.u8 %0,%1;" : "=f"(o) : "h"(t));
    return o;
}

__global__ __launch_bounds__(240, 6)
void vtm_down_kernel(const float* __restrict__ x, float* __restrict__ out) {
    const int bc = blockIdx.y;            // image 0..23
    const int B  = blockIdx.x;            // 8-output-row band, 0..67

    __shared__ __align__(16) float vv[NC][VS];

    const int tid = threadIdx.x;
    const float* xim = x + bc * (IH * IW);      // all offsets < 2^31
    const int r0 = 2 * B - 2;

    // ---- Stage A: vertical per column (threads 0..239 -> col tid; 0..2 also 240+tid)
    #pragma unroll
    for (int pass = 0; pass < 2; pass++) {
        const int u = pass == 0 ? tid : 240 + tid;
        if (pass == 0 || tid < NC - 240) {
            float p[7];
            #pragma unroll
            for (int r = 0; r < 7; r++) {
                int gr = r0 + r; if (gr < 0) gr = 0;   // top clamp (B==0 only)
                p[r] = __ldg(&xim[gr * IW + u]);
            }
            #pragma unroll
            for (int bl = 0; bl < 2; bl++) {
                float4 v;
                v.x = p[bl + 2];                                       // q=0: raw (128x folded)
                v.y = U1(p[bl], p[bl+1], p[bl+2], p[bl+3], p[bl+4], p[bl+5]);
                v.z = U2(p[bl], p[bl+1], p[bl+2], p[bl+3], p[bl+4], p[bl+5]);
                v.w = U3(p[bl], p[bl+1], p[bl+2], p[bl+3], p[bl+4], p[bl+5]);
                *(float4*)&vv[u][4 * bl] = v;                          // STS.128
            }
        }
    }
    __syncthreads();

    // ---- Stage B: horizontal per output col-tile (u = tid), 2 bands ----
    const int c0 = tid < 2 ? 0 : tid - 2;       // left clamp (tid<2 only)
    const int c1 = tid < 1 ? 0 : tid - 1;
    float* oim = out + bc * (OH * OW) + (8 * B) * OW + tid * 4;

    #pragma unroll
    for (int bl = 0; bl < 2; bl++) {
        if (8 * B + 4 * bl < OH) {              // guards only B==67's second band
            const float4 w0 = *(const float4*)&vv[c0][4 * bl];     // LDS.128, conflict-free
            const float4 w1 = *(const float4*)&vv[c1][4 * bl];
            const float4 w2 = *(const float4*)&vv[tid][4 * bl];
            const float4 w3 = *(const float4*)&vv[tid + 1][4 * bl];
            const float4 w4 = *(const float4*)&vv[tid + 2][4 * bl];
            const float4 w5 = *(const float4*)&vv[tid + 3][4 * bl];

            float* op = oim + 4 * bl * OW;
            float4 o;
            // q = 0 row (v raw -> coeffs * 2^-7); (q0,p0) output == input pixel
            o.x = w2.x;
            o.y = fin(Q1(S7, w0.x, w1.x, w2.x, w3.x, w4.x, w5.x));
            o.z = fin(Q2(S7, w0.x, w1.x, w2.x, w3.x, w4.x, w5.x));
            o.w = fin(Q3(S7, w0.x, w1.x, w2.x, w3.x, w4.x, w5.x));
            *(float4*)op = o;
            // q = 1 row
            o.x = fin(fmaf(128.f * S14, w2.y, 0.5f));
            o.y = fin(Q1(S14, w0.y, w1.y, w2.y, w3.y, w4.y, w5.y));
            o.z = fin(Q2(S14, w0.y, w1.y, w2.y, w3.y, w4.y, w5.y));
            o.w = fin(Q3(S14, w0.y, w1.y, w2.y, w3.y, w4.y, w5.y));
            *(float4*)(op + OW) = o;
            // q = 2 row
            o.x = fin(fmaf(128.f * S14, w2.z, 0.5f));
            o.y = fin(Q1(S14, w0.z, w1.z, w2.z, w3.z, w4.z, w5.z));
            o.z = fin(Q2(S14, w0.z, w1.z, w2.z, w3.z, w4.z, w5.z));
            o.w = fin(Q3(S14, w0.z, w1.z, w2.z, w3.z, w4.z, w5.z));
            *(float4*)(op + 2 * OW) = o;
            // q = 3 row
            o.x = fin(fmaf(128.f * S14, w2.w, 0.5f));
            o.y = fin(Q1(S14, w0.w, w1.w, w2.w, w3.w, w4.w, w5.w));
            o.z = fin(Q2(S14, w0.w, w1.w, w2.w, w3.w, w4.w, w5.w));
            o.w = fin(Q3(S14, w0.w, w1.w, w2.w, w3.w, w4.w, w5.w));
            *(float4*)(op + 3 * OW) = o;
        }
    }
}

extern "C" void kernel_launch(void* const* d_in, const int* in_sizes, int n_in,
                              void* d_out, int out_size) {
    const float* x = (const float*)d_in[0];
    float* out = (float*)d_out;
    dim3 grid((OH + 7) / 8, NIMG);        // 68 x 24 = 1632 blocks
    vtm_down_kernel<<<grid, 240>>>(x, out);
}

// round 17
// speedup vs baseline: 1.0201x; 1.0201x over previous
#include <cuda_runtime.h>
#include <stdint.h>

// VTM downsampler — VERTICAL-FIRST, 16 output rows/block, single wave.
// Stage A: per input column, vertical 6-tap (4 phases x 4 bands, unscaled) ->
//          smem vv[col][20] (slots bl*4+q; 80B stride = conflict-free LDS.128).
// Stage B: per output col-tile, horizontal 6-tap on vv, per band (register
//          pressure independent of band count — windows reloaded per band).
// Order swap exact: all sums integers < 2^24; reference's inter-pass trunc is
// a no-op. Coeffs pre-scaled by 2^-14 (2^-7 on vertical-delta row, absorbing
// its 128x), bias 0.5 seeded; cvt.rzi.sat.u8 == clip(floor(.),0,255).
//
// integer = i>>2, frac = 4*(i&3) -> FILTER rows {0,4,8,12}, taps k=3..8.

#define IH 1080
#define IW 1920
#define OH 540
#define OW 960
#define NIMG 24
#define NC 243           // input cols 0..242 ever needed
#define VS 20            // slots per col (16 used); 80B stride, conflict-free

#define S14 6.103515625e-5f   // 2^-14
#define S7  7.8125e-3f        // 2^-7 (vertical-delta row: 128x folded in)

// 6-tap chains, coeffs scaled by S, bias 0.5 seeded (horizontal phases 1,2,3)
#define Q1(S,a0,a1,a2,a3,a4,a5) fmaf(5.f*(S),(a0), fmaf(-18.f*(S),(a1), fmaf(114.f*(S),(a2), \
                                 fmaf(36.f*(S),(a3), fmaf(-10.f*(S),(a4), fmaf((S),(a5),0.5f))))))
#define Q2(S,a0,a1,a2,a3,a4,a5) fmaf(4.f*(S),((a0)+(a5)), fmaf(-19.f*(S),((a1)+(a4)), \
                                 fmaf(79.f*(S),((a2)+(a3)),0.5f)))
#define Q3(S,a0,a1,a2,a3,a4,a5) fmaf(5.f*(S),(a5), fmaf(-18.f*(S),(a4), fmaf(114.f*(S),(a3), \
                                 fmaf(36.f*(S),(a2), fmaf(-10.f*(S),(a1), fmaf((S),(a0),0.5f))))))
// unscaled integer chains (vertical, stage A)
#define U1(a0,a1,a2,a3,a4,a5) fmaf(5.f,(a0), fmaf(-18.f,(a1), fmaf(114.f,(a2), \
                              fmaf(36.f,(a3), fmaf(-10.f,(a4),(a5))))))
#define U2(a0,a1,a2,a3,a4,a5) fmaf(4.f,((a0)+(a5)), fmaf(-19.f,((a1)+(a4)), 79.f*((a2)+(a3))))
#define U3(a0,a1,a2,a3,a4,a5) fmaf(5.f,(a5), fmaf(-18.f,(a4), fmaf(114.f,(a3), \
                              fmaf(36.f,(a2), fmaf(-10.f,(a1),(a0))))))

// clip(floor(v),0,255) via saturating u8 truncate
__device__ __forceinline__ float fin(float v) {
    unsigned short t; asm("cvt.rzi.sat.u8.f32 %0,%1;" : "=h"(t) : "f"(v));
    float o;          asm("cvt.rn.f32.u8 %0,%1;" : "=f"(o) : "h"(t));
    return o;
}

__global__ __launch_bounds__(240, 6)
void vtm_down_kernel(const float* __restrict__ x, float* __restrict__ out) {
    const int bc = blockIdx.y;            // image 0..23
    const int B  = blockIdx.x;            // 16-output-row chunk, 0..33

    __shared__ __align__(16) float vv[NC][VS];

    const int tid = threadIdx.x;
    const float* xim = x + bc * (IH * IW);      // all offsets < 2^31
    const int r0 = 4 * B - 2;             // input row of slot 0 (max 4*33+6=138<1080)

    // ---- Stage A: vertical per column; 240 threads cover 243 cols in 2 passes
    #pragma unroll
    for (int pass = 0; pass < 2; pass++) {
        const int u = pass == 0 ? tid : 240 + tid;
        if (pass == 0 || tid < NC - 240) {
            float p[9];
            #pragma unroll
            for (int r = 0; r < 9; r++) {
                int gr = r0 + r; if (gr < 0) gr = 0;   // top clamp (B==0 only)
                p[r] = __ldg(&xim[gr * IW + u]);
            }
            #pragma unroll
            for (int bl = 0; bl < 4; bl++) {
                float4 v;
                v.x = p[bl + 2];                       // q=0: raw (128x folded later)
                v.y = U1(p[bl], p[bl+1], p[bl+2], p[bl+3], p[bl+4], p[bl+5]);
                v.z = U2(p[bl], p[bl+1], p[bl+2], p[bl+3], p[bl+4], p[bl+5]);
                v.w = U3(p[bl], p[bl+1], p[bl+2], p[bl+3], p[bl+4], p[bl+5]);
                *(float4*)&vv[u][4 * bl] = v;          // STS.128
            }
        }
    }
    __syncthreads();

    // ---- Stage B: horizontal per output col-tile (u = tid), 4 bands ----
    const int c0 = tid < 2 ? 0 : tid - 2;       // left clamp (tid<2 only)
    const int c1 = tid < 1 ? 0 : tid - 1;
    float* oim = out + bc * (OH * OW) + (16 * B) * OW + tid * 4;

    #pragma unroll
    for (int bl = 0; bl < 4; bl++) {
        if (16 * B + 4 * bl < OH) {              // skips only B==33's band 3
            const float4 w0 = *(const float4*)&vv[c0][4 * bl];     // LDS.128
            const float4 w1 = *(const float4*)&vv[c1][4 * bl];
            const float4 w2 = *(const float4*)&vv[tid][4 * bl];
            const float4 w3 = *(const float4*)&vv[tid + 1][4 * bl];
            const float4 w4 = *(const float4*)&vv[tid + 2][4 * bl];
            const float4 w5 = *(const float4*)&vv[tid + 3][4 * bl];

            float* op = oim + 4 * bl * OW;
            float4 o;
            // q = 0 row (raw verticals -> 2^-7 coeffs); (q0,p0) == input pixel
            o.x = w2.x;
            o.y = fin(Q1(S7, w0.x, w1.x, w2.x, w3.x, w4.x, w5.x));
            o.z = fin(Q2(S7, w0.x, w1.x, w2.x, w3.x, w4.x, w5.x));
            o.w = fin(Q3(S7, w0.x, w1.x, w2.x, w3.x, w4.x, w5.x));
            *(float4*)op = o;
            // q = 1 row
            o.x = fin(fmaf(128.f * S14, w2.y, 0.5f));
            o.y = fin(Q1(S14, w0.y, w1.y, w2.y, w3.y, w4.y, w5.y));
            o.z = fin(Q2(S14, w0.y, w1.y, w2.y, w3.y, w4.y, w5.y));
            o.w = fin(Q3(S14, w0.y, w1.y, w2.y, w3.y, w4.y, w5.y));
            *(float4*)(op + OW) = o;
            // q = 2 row
            o.x = fin(fmaf(128.f * S14, w2.z, 0.5f));
            o.y = fin(Q1(S14, w0.z, w1.z, w2.z, w3.z, w4.z, w5.z));
            o.z = fin(Q2(S14, w0.z, w1.z, w2.z, w3.z, w4.z, w5.z));
            o.w = fin(Q3(S14, w0.z, w1.z, w2.z, w3.z, w4.z, w5.z));
            *(float4*)(op + 2 * OW) = o;
            // q = 3 row
            o.x = fin(fmaf(128.f * S14, w2.w, 0.5f));
            o.y = fin(Q1(S14, w0.w, w1.w, w2.w, w3.w, w4.w, w5.w));
            o.z = fin(Q2(S14, w0.w, w1.w, w2.w, w3.w, w4.w, w5.w));
            o.w = fin(Q3(S14, w0.w, w1.w, w2.w, w3.w, w4.w, w5.w));
            *(float4*)(op + 3 * OW) = o;
        }
    }
}

extern "C" void kernel_launch(void* const* d_in, const int* in_sizes, int n_in,
                              void* d_out, int out_size) {
    const float* x = (const float*)d_in[0];
    float* out = (float*)d_out;
    dim3 grid(34, NIMG);                  // 816 blocks <= 888 resident: one wave
    vtm_down_kernel<<<grid, 240>>>(x, out);
}